// round 16
// baseline (speedup 1.0000x reference)
#include <cuda_runtime.h>
#include <math.h>

#define NB   4
#define LEN  64
#define DM   128
#define DI   256
#define DS   16
#define DTR  8
#define EPSF 1e-5f
#define NBLK 64
#define NTHR 512
#define BPB  16          // blocks per batch
#define HT   7           // 3 halo + 4 own tokens

// ------------------------- device scratch (no allocs) -------------------------
__device__ __align__(16) float g_rA [NB*LEN*DM];   // residual ping
__device__ __align__(16) float g_rB [NB*LEN*DM];   // residual pong
__device__ __align__(16) float g_ucm[NB*DI*LEN];   // u=silu(conv)  [b][c][t]
__device__ __align__(16) float g_zs [NB*DI*LEN];   // silu(z)       [b][c][t]
__device__ __align__(16) float g_dt [NB*DI*LEN];   // softplus dt   [b][c][t]
__device__ __align__(16) float g_ys [NB*LEN*DI];   // y*silu(z)     [b][t][c]
__device__ __align__(16) float g_Bm [NB*LEN*DS];   // [b][t][n]
__device__ __align__(16) float g_Cm [NB*LEN*DS];   // [b][t][n]

// per-batch barrier state, padded 128B apart
__device__ unsigned g_cnt[NB*32];
__device__ unsigned g_gen[NB*32];

__device__ __forceinline__ float siluf(float x){ return x / (1.0f + __expf(-x)); }
__device__ __forceinline__ float geluf(float x){ return 0.5f*x*(1.0f + erff(x*0.70710678118654752f)); }
__device__ __forceinline__ float softplusf(float x){ return x > 20.0f ? x : log1pf(expf(x)); }

__device__ __forceinline__ void st_rel(unsigned* p, unsigned v){
    asm volatile("st.global.release.gpu.u32 [%0], %1;" :: "l"(p), "r"(v) : "memory");
}
__device__ __forceinline__ unsigned ld_acq(unsigned* p){
    unsigned v;
    asm volatile("ld.global.acquire.gpu.u32 %0, [%1];" : "=r"(v) : "l"(p) : "memory");
    return v;
}

// per-batch monotonic-epoch barrier: 16 arrivals
__device__ __forceinline__ void gbar(int b, unsigned k)
{
    __syncthreads();
    if (threadIdx.x == 0){
        __threadfence();
        unsigned prev = atomicAdd(&g_cnt[b*32], 1u);
        if (prev == k*BPB - 1u){
            st_rel(&g_gen[b*32], k);
        } else {
            while ((int)(ld_acq(&g_gen[b*32]) - k) < 0) {}
        }
    }
    __syncthreads();
}

// Coalesced k-split GEMM, float accumulators. 16 warps.
// W row-major [*][K]; rows [r0, r0+Rn) (Rn multiple of 64 or single guarded tile);
// xs smem [T][xstr]; dst[t*dstr + row - r0] (+bias, optional gelu).
// warp = 4 row-groups x 8 k-lanes; each LDG.128 touches 4 lines (minimum).
template<int K, int T, bool GELU>
__device__ __forceinline__ void gemmF(const float* __restrict__ W, int r0, int Rn,
                                      const float* xs, int xstr,
                                      float* dst, int dstr,
                                      const float* __restrict__ bias, int tid)
{
    const int wid = tid >> 5;          // 0..15
    const int rg  = (tid >> 3) & 3;
    const int kg  = tid & 7;
    for (int tile = 0; tile < Rn; tile += 64){
        const int row = r0 + tile + wid*4 + rg;
        const float4* wr = (const float4*)(W + (size_t)row*K + kg*4);
        float acc[T];
        #pragma unroll
        for (int t = 0; t < T; t++) acc[t] = 0.0f;
        #pragma unroll 4
        for (int it = 0; it < K/32; it++){
            float4 w = wr[it*8];
            #pragma unroll
            for (int t = 0; t < T; t++){
                float4 v = *(const float4*)(xs + t*xstr + it*32 + kg*4);
                acc[t] += w.x*v.x + w.y*v.y + w.z*v.z + w.w*v.w;
            }
        }
        #pragma unroll
        for (int t = 0; t < T; t++){
            float a = acc[t];
            a += __shfl_xor_sync(0xffffffffu, a, 1, 8);
            a += __shfl_xor_sync(0xffffffffu, a, 2, 8);
            a += __shfl_xor_sync(0xffffffffu, a, 4, 8);
            if (kg == 0){
                if (bias) a += bias[row - r0];
                if (GELU) a = geluf(a);
                dst[t*dstr + (row - r0)] = a;
            }
        }
    }
}

// smem float offsets
#define OFF_STG 0        // [7][256] ys stage; L0: mha [7][128]
#define OFF_H1  896
#define OFF_R   1792     // [7][128]
#define OFF_HN  2688     // [7][128]
#define OFF_XC  3584     // [7][256]
#define OFF_U   5376     // [4][256]
#define OFF_DT  6400     // [4][8]
// scan layout (aliases; separated by barrier)
#define SC_DT   0
#define SC_U    1152
#define SC_Z    2304
#define SC_B    3456
#define SC_C    4480
#define SMSZ    6432

__global__ void __launch_bounds__(NTHR) mamba_fused(
    const float* __restrict__ mha, const unsigned char* __restrict__ mask,
    const float* __restrict__ w1,  const float* __restrict__ b1,
    const float* __restrict__ w2,  const float* __restrict__ b2,
    const float* __restrict__ inw, const float* __restrict__ cw,
    const float* __restrict__ cb,  const float* __restrict__ xpw,
    const float* __restrict__ dtw, const float* __restrict__ dtb,
    const float* __restrict__ alg, const float* __restrict__ dsk,
    const float* __restrict__ ow,  const float* __restrict__ bnw,
    const float* __restrict__ nfw, float* __restrict__ out)
{
    const int blk = blockIdx.x, tid = threadIdx.x;
    const int b   = blk >> 4;
    const int tg  = blk & 15;
    const int t0  = tg * 4;
    __shared__ __align__(16) float buf[SMSZ];
    __shared__ float sSum[8];
    __shared__ unsigned sVal[2];
    unsigned k = ld_acq(&g_gen[b*32]);

    // ================================ layers ================================
    for (int L = 0; L < 4; L++){
        // ---------- fused: (MLP | out_proj+res) + rmsnorm + in_proj + conv + x_proj + dt ----------
        if (L == 0){
            // stage mha 7 tokens [7][128]
            for (int i = tid; i < HT*32; i += NTHR){
                const int tk = i >> 5, q = i & 31, t = t0 - 3 + tk;
                float4 v = make_float4(0,0,0,0);
                if (t >= 0) v = ((const float4*)(mha + ((size_t)(b*4096 + t))*DM))[q];
                ((float4*)(buf + OFF_STG))[i] = v;
            }
            __syncthreads();
            gemmF<128,7,true >(w1, 0, 128, buf + OFF_STG, 128, buf + OFF_H1, 128, b1, tid);
            __syncthreads();
            gemmF<128,7,false>(w2, 0, 128, buf + OFF_H1, 128, buf + OFF_R, 128, b2, tid);
        } else {
            // stage ys 7 tokens [7][256]
            for (int i = tid; i < HT*64; i += NTHR){
                const int tk = i >> 6, q = i & 63, t = t0 - 3 + tk;
                float4 v = make_float4(0,0,0,0);
                if (t >= 0) v = __ldcg((const float4*)(g_ys + (size_t)(b*LEN + t)*DI) + q);
                ((float4*)(buf + OFF_STG))[i] = v;
            }
            __syncthreads();
            gemmF<256,7,false>(ow + (size_t)(L-1)*DM*DI, 0, 128,
                               buf + OFF_STG, 256, buf + OFF_R, 128, nullptr, tid);
        }
        __syncthreads();
        // residual combine: stride loop over 7x128 elements
        {
            const float* rIn = (L & 1) ? g_rA : g_rB;
            float* rOut = (L & 1) ? g_rB : g_rA;
            for (int i = tid; i < HT*DM; i += NTHR){
                const int s = i >> 7, jj = i & 127;
                const int t = t0 - 3 + s;
                float v = buf[OFF_R + i];
                if (t >= 0 && L > 0) v += __ldcg(rIn + (b*LEN + t)*DM + jj);
                v = (t >= 0) ? v : 0.0f;
                buf[OFF_R + i] = v;
                if (s >= 3) rOut[(b*LEN + t)*DM + jj] = v;
            }
        }
        __syncthreads();
        // rmsnorm sums: warp w -> token w (7 tokens; warps 7-15 idle)
        {
            const int w = tid >> 5, lane = tid & 31;
            if (w < HT){
                float v0 = buf[OFF_R + w*DM + lane];
                float v1 = buf[OFF_R + w*DM + lane + 32];
                float v2 = buf[OFF_R + w*DM + lane + 64];
                float v3 = buf[OFF_R + w*DM + lane + 96];
                float s = v0*v0 + v1*v1 + v2*v2 + v3*v3;
                #pragma unroll
                for (int o = 16; o > 0; o >>= 1) s += __shfl_xor_sync(0xffffffffu, s, o);
                if (lane == 0) sSum[w] = s;
            }
        }
        __syncthreads();
        for (int i = tid; i < HT*DM; i += NTHR){
            const int s = i >> 7, jj = i & 127;
            buf[OFF_HN + i] = buf[OFF_R + i] * rsqrtf(sSum[s]*(1.0f/DM) + EPSF) * bnw[L*DM + jj];
        }
        __syncthreads();
        // in_proj: xc rows 0..255 x 7 tokens -> OFF_XC; z rows 256..511 x 4 own tokens -> OFF_U raw
        const float* Wi = inw + (size_t)L*2*DI*DM;
        gemmF<128,7,false>(Wi, 0, 256, buf + OFF_HN, 128, buf + OFF_XC, 256, nullptr, tid);
        gemmF<128,4,false>(Wi, 256, 256, buf + OFF_HN + 3*128, 128, buf + OFF_U, 256, nullptr, tid);
        __syncthreads();
        // z writeout: silu + store c-major (1 channel per thread, tid<256)
        if (tid < 256){
            const int c = tid;
            float4 zz = make_float4(siluf(buf[OFF_U + 0*DI + c]), siluf(buf[OFF_U + 1*DI + c]),
                                    siluf(buf[OFF_U + 2*DI + c]), siluf(buf[OFF_U + 3*DI + c]));
            *(float4*)(g_zs + (b*DI + c)*LEN + t0) = zz;
        }
        __syncthreads();
        // conv width-4 + silu: 1 channel per thread (overwrites OFF_U)
        if (tid < 256){
            const int c = tid;
            float4 wv = *(const float4*)(cw + ((size_t)L*DI + c)*4);
            const float bb = cb[L*DI + c];
            float xv[HT];
            #pragma unroll
            for (int s = 0; s < HT; s++) xv[s] = buf[OFF_XC + s*DI + c];
            float u4[4];
            #pragma unroll
            for (int jj = 0; jj < 4; jj++){
                float y = bb + wv.x*xv[jj] + wv.y*xv[jj+1] + wv.z*xv[jj+2] + wv.w*xv[jj+3];
                u4[jj] = siluf(y);
            }
            #pragma unroll
            for (int jj = 0; jj < 4; jj++) buf[OFF_U + jj*DI + c] = u4[jj];
            *(float4*)(g_ucm + (b*DI + c)*LEN + t0) =
                make_float4(u4[0], u4[1], u4[2], u4[3]);
        }
        __syncthreads();
        // x_proj: 40 rows x 4 tokens, one guarded 64-row tile (16 warps)
        {
            const float* xw = xpw + (size_t)L*(DTR + 2*DS)*DI;
            const int wid = tid >> 5, rg = (tid >> 3) & 3, kg = tid & 7;
            const int row  = wid*4 + rg;                  // 0..63
            const int rowc = row < 40 ? row : 39;
            const float4* wr = (const float4*)(xw + (size_t)rowc*DI + kg*4);
            float acc[4] = {0,0,0,0};
            #pragma unroll 4
            for (int it = 0; it < 8; it++){
                float4 w = wr[it*8];
                #pragma unroll
                for (int t = 0; t < 4; t++){
                    float4 v = *(const float4*)(buf + OFF_U + t*DI + it*32 + kg*4);
                    acc[t] += w.x*v.x + w.y*v.y + w.z*v.z + w.w*v.w;
                }
            }
            #pragma unroll
            for (int t = 0; t < 4; t++){
                float a = acc[t];
                a += __shfl_xor_sync(0xffffffffu, a, 1, 8);
                a += __shfl_xor_sync(0xffffffffu, a, 2, 8);
                a += __shfl_xor_sync(0xffffffffu, a, 4, 8);
                if (kg == 0 && row < 40){
                    const int t_g = t0 + t;
                    if (row < DTR)            buf[OFF_DT + t*DTR + row] = a;
                    else if (row < DTR + DS)  g_Bm[(b*LEN + t_g)*DS + (row - DTR)]      = a;
                    else                      g_Cm[(b*LEN + t_g)*DS + (row - DTR - DS)] = a;
                }
            }
        }
        __syncthreads();
        // dt_proj + softplus: 1 channel per thread (tid<256)
        if (tid < 256){
            const int c = tid;
            const float* dw = dtw + (size_t)L*DI*DTR;
            float bb = dtb[L*DI + c];
            float wreg[DTR];
            #pragma unroll
            for (int q = 0; q < DTR; q++) wreg[q] = dw[c*DTR + q];
            float d4[4];
            #pragma unroll
            for (int tk = 0; tk < 4; tk++){
                float a = bb;
                #pragma unroll
                for (int q = 0; q < DTR; q++) a += buf[OFF_DT + tk*DTR + q] * wreg[q];
                d4[tk] = softplusf(a);
            }
            *(float4*)(g_dt + (b*DI + c)*LEN + t0) =
                make_float4(d4[0], d4[1], d4[2], d4[3]);
        }
        gbar(b, ++k);

        // ---------- scan: block=(b, 16-ch slice); thread=(cs, n) 1 state (tid<256) ----------
        {
            const int c0 = tg*16;
            if (tid < 256){
                const int cs = tid >> 4, q = tid & 15;
                *(float4*)(buf + SC_DT + cs*72 + q*4) =
                    __ldcg((const float4*)(g_dt  + (b*DI + c0 + cs)*LEN) + q);
                *(float4*)(buf + SC_U  + cs*72 + q*4) =
                    __ldcg((const float4*)(g_ucm + (b*DI + c0 + cs)*LEN) + q);
                *(float4*)(buf + SC_Z  + cs*72 + q*4) =
                    __ldcg((const float4*)(g_zs  + (b*DI + c0 + cs)*LEN) + q);
                ((float4*)(buf + SC_B))[tid] = __ldcg((const float4*)(g_Bm + b*LEN*DS) + tid);
                ((float4*)(buf + SC_C))[tid] = __ldcg((const float4*)(g_Cm + b*LEN*DS) + tid);
            }
            __syncthreads();
            if (tid < 256){
                const int cs = tid >> 4, n = tid & 15, c = c0 + cs;
                const float A  = -expf(alg[((size_t)L*DI + c)*DS + n]);
                const float Dv = dsk[L*DI + c];
                const float* pd = buf + SC_DT + cs*72;
                const float* pu = buf + SC_U  + cs*72;
                const float* pz = buf + SC_Z  + cs*72;
                float h = 0.0f;
                for (int tq = 0; tq < 16; tq++){
                    const int tb = tq*4;
                    float4 dt4 = *(const float4*)(pd + tb);
                    float4 u4  = *(const float4*)(pu + tb);
                    const float* dta = (const float*)&dt4;
                    const float* ua  = (const float*)&u4;
                    float dA[4], y[4];
                    #pragma unroll
                    for (int s = 0; s < 4; s++) dA[s] = __expf(dta[s] * A);
                    #pragma unroll
                    for (int s = 0; s < 4; s++){
                        h = h*dA[s] + (dta[s]*ua[s]) * buf[SC_B + (tb+s)*DS + n];
                        y[s] = h * buf[SC_C + (tb+s)*DS + n];
                    }
                    #pragma unroll
                    for (int o = 1; o < 16; o <<= 1){
                        #pragma unroll
                        for (int s = 0; s < 4; s++)
                            y[s] += __shfl_xor_sync(0xffffffffu, y[s], o, 16);
                    }
                    if (n == 0){
                        #pragma unroll
                        for (int s = 0; s < 4; s++)
                            g_ys[(b*LEN + tb + s)*DI + c] = (y[s] + ua[s]*Dv) * pz[tb + s];
                    }
                }
            }
            __syncthreads();
        }
        gbar(b, ++k);
    }

    // ---------------- final: out_proj(L3) t=63 + residual + rmsnorm + mask ----------------
    if (tg == 15){
        if (tid < 64)
            ((float4*)buf)[tid] = __ldcg((const float4*)(g_ys + (size_t)(b*LEN + 63)*DI) + tid);
        __syncthreads();
        gemmF<256,1,false>(ow + (size_t)3*DM*DI, 0, 128, buf, 256, buf + 512, 128, nullptr, tid);
        __syncthreads();
        float rv = 0.0f;
        if (tid < 128){
            rv = buf[512 + tid] + g_rB[(b*LEN + 63)*DM + tid];   // own write at L3
            float s = rv*rv;
            #pragma unroll
            for (int o = 16; o > 0; o >>= 1) s += __shfl_xor_sync(0xffffffffu, s, o);
            if ((tid & 31) == 0) sSum[tid >> 5] = s;
        }
        {
            unsigned v = 0;
            if (tid < 64) v = (mask[b*4096 + tid] != 0) ? 1u : 0u;   // row (b, n=0, :)
            unsigned bal = __ballot_sync(0xffffffffu, v != 0u);
            if (tid < 64 && (tid & 31) == 0) sVal[tid >> 5] = bal;
        }
        __syncthreads();
        if (tid < 128){
            const int valid = ((sVal[0] | sVal[1]) != 0u) ? 1 : 0;
            float s = sSum[0] + sSum[1] + sSum[2] + sSum[3];
            float o = rv * rsqrtf(s*(1.0f/DM) + EPSF) * nfw[tid];
            out[b*DM + tid] = valid ? o : 0.0f;
        }
    }
}

// --------------------------------- launch ---------------------------------
extern "C" void kernel_launch(void* const* d_in, const int* in_sizes, int n_in,
                              void* d_out, int out_size)
{
    const float* mha = (const float*)d_in[0];
    const unsigned char* mask = (const unsigned char*)d_in[1];
    const float* w1  = (const float*)d_in[2];
    const float* b1  = (const float*)d_in[3];
    const float* w2  = (const float*)d_in[4];
    const float* b2  = (const float*)d_in[5];
    const float* inw = (const float*)d_in[6];
    const float* cw  = (const float*)d_in[7];
    const float* cb  = (const float*)d_in[8];
    const float* xpw = (const float*)d_in[9];
    const float* dtw = (const float*)d_in[10];
    const float* dtb = (const float*)d_in[11];
    const float* alg = (const float*)d_in[12];
    const float* dsk = (const float*)d_in[13];
    const float* ow  = (const float*)d_in[14];
    const float* bnw = (const float*)d_in[15];
    const float* nfw = (const float*)d_in[16];
    float* out = (float*)d_out;

    mamba_fused<<<NBLK, NTHR>>>(mha, mask, w1, b1, w2, b2, inw, cw, cb,
                                xpw, dtw, dtb, alg, dsk, ow, bnw, nfw, out);
}

// round 17
// speedup vs baseline: 1.2627x; 1.2627x over previous
#include <cuda_runtime.h>
#include <math.h>

#define NB   4
#define LEN  64
#define DM   128
#define DI   256
#define DS   16
#define DTR  8
#define EPSF 1e-5f
#define NBLK 64
#define NTHR 512
#define BPB  16          // blocks per batch
#define HT   7           // 3 halo + 4 own tokens

// ------------------------- device scratch (no allocs) -------------------------
__device__ __align__(16) float g_rA [NB*LEN*DM];   // residual ping
__device__ __align__(16) float g_rB [NB*LEN*DM];   // residual pong
__device__ __align__(16) float g_ucm[NB*DI*LEN];   // u=silu(conv)  [b][c][t]
__device__ __align__(16) float g_zs [NB*DI*LEN];   // silu(z)       [b][c][t]
__device__ __align__(16) float g_dt [NB*DI*LEN];   // softplus dt   [b][c][t]
__device__ __align__(16) float g_ys [NB*LEN*DI];   // y*silu(z)     [b][t][c]
__device__ __align__(16) float g_Bm [NB*LEN*DS];   // [b][t][n]
__device__ __align__(16) float g_Cm [NB*LEN*DS];   // [b][t][n]

// per-batch barrier state, padded 128B apart
__device__ unsigned g_cnt[NB*32];
__device__ unsigned g_gen[NB*32];

__device__ __forceinline__ float siluf(float x){ return x / (1.0f + __expf(-x)); }
__device__ __forceinline__ float geluf(float x){ return 0.5f*x*(1.0f + erff(x*0.70710678118654752f)); }
__device__ __forceinline__ float softplusf(float x){ return x > 20.0f ? x : log1pf(expf(x)); }

__device__ __forceinline__ void st_rel(unsigned* p, unsigned v){
    asm volatile("st.global.release.gpu.u32 [%0], %1;" :: "l"(p), "r"(v) : "memory");
}
__device__ __forceinline__ unsigned ld_acq(unsigned* p){
    unsigned v;
    asm volatile("ld.global.acquire.gpu.u32 %0, [%1];" : "=r"(v) : "l"(p) : "memory");
    return v;
}

// per-batch monotonic-epoch barrier: 16 arrivals
__device__ __forceinline__ void gbar(int b, unsigned k)
{
    __syncthreads();
    if (threadIdx.x == 0){
        __threadfence();
        unsigned prev = atomicAdd(&g_cnt[b*32], 1u);
        if (prev == k*BPB - 1u){
            st_rel(&g_gen[b*32], k);
        } else {
            while ((int)(ld_acq(&g_gen[b*32]) - k) < 0) {}
        }
    }
    __syncthreads();
}

// Register-cached coalesced k-split GEMM. 16 warps.
// W row-major [*][K]; rows [r0, r0 + TILES*64); xs smem [T][xstr];
// dst[t*dstr + row - r0] (+bias, optional gelu).
// k-chunk OUTER loop: xv[T] loaded from smem once per chunk, reused across
// TILES row tiles (LDS count / TILES vs naive). Each LDG.128 touches 4 lines.
template<int K, int T, int TILES, bool GELU>
__device__ __forceinline__ void gemmR(const float* __restrict__ W, int r0,
                                      const float* xs, int xstr,
                                      float* dst, int dstr,
                                      const float* __restrict__ bias, int tid)
{
    const int wid = tid >> 5;          // 0..15
    const int rg  = (tid >> 3) & 3;
    const int kg  = tid & 7;
    const int rb  = wid*4 + rg;        // row within tile (0..63)
    const float4* wr[TILES];
    #pragma unroll
    for (int i = 0; i < TILES; i++)
        wr[i] = (const float4*)(W + (size_t)(r0 + i*64 + rb)*K + kg*4);
    float acc[TILES][T];
    #pragma unroll
    for (int i = 0; i < TILES; i++)
        #pragma unroll
        for (int t = 0; t < T; t++) acc[i][t] = 0.0f;
    #pragma unroll 2
    for (int it = 0; it < K/32; it++){
        float4 xv[T];
        #pragma unroll
        for (int t = 0; t < T; t++)
            xv[t] = *(const float4*)(xs + t*xstr + it*32 + kg*4);
        #pragma unroll
        for (int i = 0; i < TILES; i++){
            float4 w = wr[i][it*8];
            #pragma unroll
            for (int t = 0; t < T; t++)
                acc[i][t] += w.x*xv[t].x + w.y*xv[t].y + w.z*xv[t].z + w.w*xv[t].w;
        }
    }
    #pragma unroll
    for (int i = 0; i < TILES; i++){
        #pragma unroll
        for (int t = 0; t < T; t++){
            float a = acc[i][t];
            a += __shfl_xor_sync(0xffffffffu, a, 1, 8);
            a += __shfl_xor_sync(0xffffffffu, a, 2, 8);
            a += __shfl_xor_sync(0xffffffffu, a, 4, 8);
            if (kg == 0){
                const int ro = i*64 + rb;
                if (bias) a += bias[ro];
                if (GELU) a = geluf(a);
                dst[t*dstr + ro] = a;
            }
        }
    }
}

// smem float offsets
#define OFF_STG 0        // [7][256] ys stage; L0: mha [7][128]
#define OFF_H1  896
#define OFF_R   1792     // [7][128]
#define OFF_HN  2688     // [7][128]
#define OFF_XC  3584     // [7][256]
#define OFF_U   5376     // [4][256]
#define OFF_DT  6400     // [4][8]
// scan layout (aliases; separated by barrier)
#define SC_DT   0
#define SC_U    1152
#define SC_Z    2304
#define SC_B    3456
#define SC_C    4480
#define SMSZ    6432

__global__ void __launch_bounds__(NTHR) mamba_fused(
    const float* __restrict__ mha, const unsigned char* __restrict__ mask,
    const float* __restrict__ w1,  const float* __restrict__ b1,
    const float* __restrict__ w2,  const float* __restrict__ b2,
    const float* __restrict__ inw, const float* __restrict__ cw,
    const float* __restrict__ cb,  const float* __restrict__ xpw,
    const float* __restrict__ dtw, const float* __restrict__ dtb,
    const float* __restrict__ alg, const float* __restrict__ dsk,
    const float* __restrict__ ow,  const float* __restrict__ bnw,
    const float* __restrict__ nfw, float* __restrict__ out)
{
    const int blk = blockIdx.x, tid = threadIdx.x;
    const int b   = blk >> 4;
    const int tg  = blk & 15;
    const int t0  = tg * 4;
    __shared__ __align__(16) float buf[SMSZ];
    __shared__ float sSum[8];
    __shared__ unsigned sVal[2];
    unsigned k = ld_acq(&g_gen[b*32]);

    // ================================ layers ================================
    for (int L = 0; L < 4; L++){
        // ---------- fused: (MLP | out_proj+res) + rmsnorm + in_proj + conv + x_proj + dt ----------
        if (L == 0){
            // stage mha 7 tokens [7][128]
            for (int i = tid; i < HT*32; i += NTHR){
                const int tk = i >> 5, q = i & 31, t = t0 - 3 + tk;
                float4 v = make_float4(0,0,0,0);
                if (t >= 0) v = ((const float4*)(mha + ((size_t)(b*4096 + t))*DM))[q];
                ((float4*)(buf + OFF_STG))[i] = v;
            }
            __syncthreads();
            gemmR<128,7,2,true >(w1, 0, buf + OFF_STG, 128, buf + OFF_H1, 128, b1, tid);
            __syncthreads();
            gemmR<128,7,2,false>(w2, 0, buf + OFF_H1, 128, buf + OFF_R, 128, b2, tid);
        } else {
            // stage ys 7 tokens [7][256]
            for (int i = tid; i < HT*64; i += NTHR){
                const int tk = i >> 6, q = i & 63, t = t0 - 3 + tk;
                float4 v = make_float4(0,0,0,0);
                if (t >= 0) v = __ldcg((const float4*)(g_ys + (size_t)(b*LEN + t)*DI) + q);
                ((float4*)(buf + OFF_STG))[i] = v;
            }
            __syncthreads();
            gemmR<256,7,2,false>(ow + (size_t)(L-1)*DM*DI, 0,
                                 buf + OFF_STG, 256, buf + OFF_R, 128, nullptr, tid);
        }
        __syncthreads();
        // residual combine: stride loop over 7x128 elements
        {
            const float* rIn = (L & 1) ? g_rA : g_rB;
            float* rOut = (L & 1) ? g_rB : g_rA;
            for (int i = tid; i < HT*DM; i += NTHR){
                const int s = i >> 7, jj = i & 127;
                const int t = t0 - 3 + s;
                float v = buf[OFF_R + i];
                if (t >= 0 && L > 0) v += __ldcg(rIn + (b*LEN + t)*DM + jj);
                v = (t >= 0) ? v : 0.0f;
                buf[OFF_R + i] = v;
                if (s >= 3) rOut[(b*LEN + t)*DM + jj] = v;
            }
        }
        __syncthreads();
        // rmsnorm sums: warp w -> token w (7 tokens; warps 7-15 idle)
        {
            const int w = tid >> 5, lane = tid & 31;
            if (w < HT){
                float v0 = buf[OFF_R + w*DM + lane];
                float v1 = buf[OFF_R + w*DM + lane + 32];
                float v2 = buf[OFF_R + w*DM + lane + 64];
                float v3 = buf[OFF_R + w*DM + lane + 96];
                float s = v0*v0 + v1*v1 + v2*v2 + v3*v3;
                #pragma unroll
                for (int o = 16; o > 0; o >>= 1) s += __shfl_xor_sync(0xffffffffu, s, o);
                if (lane == 0) sSum[w] = s;
            }
        }
        __syncthreads();
        for (int i = tid; i < HT*DM; i += NTHR){
            const int s = i >> 7, jj = i & 127;
            buf[OFF_HN + i] = buf[OFF_R + i] * rsqrtf(sSum[s]*(1.0f/DM) + EPSF) * bnw[L*DM + jj];
        }
        __syncthreads();
        // in_proj: xc rows 0..255 x 7 tokens -> OFF_XC; z rows 256..511 x 4 own tokens -> OFF_U raw
        const float* Wi = inw + (size_t)L*2*DI*DM;
        gemmR<128,7,4,false>(Wi, 0, buf + OFF_HN, 128, buf + OFF_XC, 256, nullptr, tid);
        gemmR<128,4,4,false>(Wi, 256, buf + OFF_HN + 3*128, 128, buf + OFF_U, 256, nullptr, tid);
        __syncthreads();
        // z writeout: silu + store c-major (1 channel per thread, tid<256)
        if (tid < 256){
            const int c = tid;
            float4 zz = make_float4(siluf(buf[OFF_U + 0*DI + c]), siluf(buf[OFF_U + 1*DI + c]),
                                    siluf(buf[OFF_U + 2*DI + c]), siluf(buf[OFF_U + 3*DI + c]));
            *(float4*)(g_zs + (b*DI + c)*LEN + t0) = zz;
        }
        __syncthreads();
        // conv width-4 + silu: 1 channel per thread (overwrites OFF_U)
        if (tid < 256){
            const int c = tid;
            float4 wv = *(const float4*)(cw + ((size_t)L*DI + c)*4);
            const float bb = cb[L*DI + c];
            float xv[HT];
            #pragma unroll
            for (int s = 0; s < HT; s++) xv[s] = buf[OFF_XC + s*DI + c];
            float u4[4];
            #pragma unroll
            for (int jj = 0; jj < 4; jj++){
                float y = bb + wv.x*xv[jj] + wv.y*xv[jj+1] + wv.z*xv[jj+2] + wv.w*xv[jj+3];
                u4[jj] = siluf(y);
            }
            #pragma unroll
            for (int jj = 0; jj < 4; jj++) buf[OFF_U + jj*DI + c] = u4[jj];
            *(float4*)(g_ucm + (b*DI + c)*LEN + t0) =
                make_float4(u4[0], u4[1], u4[2], u4[3]);
        }
        __syncthreads();
        // x_proj: 40 rows x 4 tokens, one guarded 64-row tile (16 warps), xv cached
        {
            const float* xw = xpw + (size_t)L*(DTR + 2*DS)*DI;
            const int wid = tid >> 5, rg = (tid >> 3) & 3, kg = tid & 7;
            const int row  = wid*4 + rg;                  // 0..63
            const int rowc = row < 40 ? row : 39;
            const float4* wr = (const float4*)(xw + (size_t)rowc*DI + kg*4);
            float acc[4] = {0,0,0,0};
            #pragma unroll 2
            for (int it = 0; it < 8; it++){
                float4 w = wr[it*8];
                #pragma unroll
                for (int t = 0; t < 4; t++){
                    float4 v = *(const float4*)(buf + OFF_U + t*DI + it*32 + kg*4);
                    acc[t] += w.x*v.x + w.y*v.y + w.z*v.z + w.w*v.w;
                }
            }
            #pragma unroll
            for (int t = 0; t < 4; t++){
                float a = acc[t];
                a += __shfl_xor_sync(0xffffffffu, a, 1, 8);
                a += __shfl_xor_sync(0xffffffffu, a, 2, 8);
                a += __shfl_xor_sync(0xffffffffu, a, 4, 8);
                if (kg == 0 && row < 40){
                    const int t_g = t0 + t;
                    if (row < DTR)            buf[OFF_DT + t*DTR + row] = a;
                    else if (row < DTR + DS)  g_Bm[(b*LEN + t_g)*DS + (row - DTR)]      = a;
                    else                      g_Cm[(b*LEN + t_g)*DS + (row - DTR - DS)] = a;
                }
            }
        }
        __syncthreads();
        // dt_proj + softplus: 1 channel per thread (tid<256)
        if (tid < 256){
            const int c = tid;
            const float* dw = dtw + (size_t)L*DI*DTR;
            float bb = dtb[L*DI + c];
            float wreg[DTR];
            #pragma unroll
            for (int q = 0; q < DTR; q++) wreg[q] = dw[c*DTR + q];
            float d4[4];
            #pragma unroll
            for (int tk = 0; tk < 4; tk++){
                float a = bb;
                #pragma unroll
                for (int q = 0; q < DTR; q++) a += buf[OFF_DT + tk*DTR + q] * wreg[q];
                d4[tk] = softplusf(a);
            }
            *(float4*)(g_dt + (b*DI + c)*LEN + t0) =
                make_float4(d4[0], d4[1], d4[2], d4[3]);
        }
        gbar(b, ++k);

        // ---------- scan: block=(b, 16-ch slice); thread=(cs, n) 1 state (tid<256) ----------
        {
            const int c0 = tg*16;
            if (tid < 256){
                const int cs = tid >> 4, q = tid & 15;
                *(float4*)(buf + SC_DT + cs*72 + q*4) =
                    __ldcg((const float4*)(g_dt  + (b*DI + c0 + cs)*LEN) + q);
                *(float4*)(buf + SC_U  + cs*72 + q*4) =
                    __ldcg((const float4*)(g_ucm + (b*DI + c0 + cs)*LEN) + q);
                *(float4*)(buf + SC_Z  + cs*72 + q*4) =
                    __ldcg((const float4*)(g_zs  + (b*DI + c0 + cs)*LEN) + q);
                ((float4*)(buf + SC_B))[tid] = __ldcg((const float4*)(g_Bm + b*LEN*DS) + tid);
                ((float4*)(buf + SC_C))[tid] = __ldcg((const float4*)(g_Cm + b*LEN*DS) + tid);
            }
            __syncthreads();
            if (tid < 256){
                const int cs = tid >> 4, n = tid & 15, c = c0 + cs;
                const float A  = -expf(alg[((size_t)L*DI + c)*DS + n]);
                const float Dv = dsk[L*DI + c];
                const float* pd = buf + SC_DT + cs*72;
                const float* pu = buf + SC_U  + cs*72;
                const float* pz = buf + SC_Z  + cs*72;
                float h = 0.0f;
                for (int tq = 0; tq < 16; tq++){
                    const int tb = tq*4;
                    float4 dt4 = *(const float4*)(pd + tb);
                    float4 u4  = *(const float4*)(pu + tb);
                    const float* dta = (const float*)&dt4;
                    const float* ua  = (const float*)&u4;
                    float dA[4], y[4];
                    #pragma unroll
                    for (int s = 0; s < 4; s++) dA[s] = __expf(dta[s] * A);
                    #pragma unroll
                    for (int s = 0; s < 4; s++){
                        h = h*dA[s] + (dta[s]*ua[s]) * buf[SC_B + (tb+s)*DS + n];
                        y[s] = h * buf[SC_C + (tb+s)*DS + n];
                    }
                    #pragma unroll
                    for (int o = 1; o < 16; o <<= 1){
                        #pragma unroll
                        for (int s = 0; s < 4; s++)
                            y[s] += __shfl_xor_sync(0xffffffffu, y[s], o, 16);
                    }
                    if (n == 0){
                        #pragma unroll
                        for (int s = 0; s < 4; s++)
                            g_ys[(b*LEN + tb + s)*DI + c] = (y[s] + ua[s]*Dv) * pz[tb + s];
                    }
                }
            }
            __syncthreads();
        }
        gbar(b, ++k);
    }

    // ---------------- final: out_proj(L3) t=63 + residual + rmsnorm + mask ----------------
    if (tg == 15){
        if (tid < 64)
            ((float4*)buf)[tid] = __ldcg((const float4*)(g_ys + (size_t)(b*LEN + 63)*DI) + tid);
        __syncthreads();
        gemmR<256,1,2,false>(ow + (size_t)3*DM*DI, 0, buf, 256, buf + 512, 128, nullptr, tid);
        __syncthreads();
        float rv = 0.0f;
        if (tid < 128){
            rv = buf[512 + tid] + g_rB[(b*LEN + 63)*DM + tid];   // own write at L3
            float s = rv*rv;
            #pragma unroll
            for (int o = 16; o > 0; o >>= 1) s += __shfl_xor_sync(0xffffffffu, s, o);
            if ((tid & 31) == 0) sSum[tid >> 5] = s;
        }
        {
            unsigned v = 0;
            if (tid < 64) v = (mask[b*4096 + tid] != 0) ? 1u : 0u;   // row (b, n=0, :)
            unsigned bal = __ballot_sync(0xffffffffu, v != 0u);
            if (tid < 64 && (tid & 31) == 0) sVal[tid >> 5] = bal;
        }
        __syncthreads();
        if (tid < 128){
            const int valid = ((sVal[0] | sVal[1]) != 0u) ? 1 : 0;
            float s = sSum[0] + sSum[1] + sSum[2] + sSum[3];
            float o = rv * rsqrtf(s*(1.0f/DM) + EPSF) * nfw[tid];
            out[b*DM + tid] = valid ? o : 0.0f;
        }
    }
}

// --------------------------------- launch ---------------------------------
extern "C" void kernel_launch(void* const* d_in, const int* in_sizes, int n_in,
                              void* d_out, int out_size)
{
    const float* mha = (const float*)d_in[0];
    const unsigned char* mask = (const unsigned char*)d_in[1];
    const float* w1  = (const float*)d_in[2];
    const float* b1  = (const float*)d_in[3];
    const float* w2  = (const float*)d_in[4];
    const float* b2  = (const float*)d_in[5];
    const float* inw = (const float*)d_in[6];
    const float* cw  = (const float*)d_in[7];
    const float* cb  = (const float*)d_in[8];
    const float* xpw = (const float*)d_in[9];
    const float* dtw = (const float*)d_in[10];
    const float* dtb = (const float*)d_in[11];
    const float* alg = (const float*)d_in[12];
    const float* dsk = (const float*)d_in[13];
    const float* ow  = (const float*)d_in[14];
    const float* bnw = (const float*)d_in[15];
    const float* nfw = (const float*)d_in[16];
    float* out = (float*)d_out;

    mamba_fused<<<NBLK, NTHR>>>(mha, mask, w1, b1, w2, b2, inw, cw, cb,
                                xpw, dtw, dtb, alg, dsk, ow, bnw, nfw, out);
}